// round 4
// baseline (speedup 1.0000x reference)
#include <cuda_runtime.h>

// ---------------------------------------------------------------------------
// DSSIM loss: 1 - mean(SSIM(X,Y)), 11x11 Gaussian (sigma=1.5), depthwise C=3,
// zero SAME padding, HWC fp32 2160x3840x3.
//
// Separable blur, row-streaming, double-buffered pipelined loads.
// Round-4: field reduction 5 -> 4 via u=x+y, v=x-y:
//   blur(u^2)+blur(v^2) = 2*(blur(xx)+blur(yy)),  blur(u^2)-blur(v^2)=4*blur(xy)
// so only two packed f32x2 blur chains: (x,y) and (u^2,v^2).
// Smem holds interleaved float4{x,y,u,v} per column -> one LDS.128 per tap.
// Padding kernels make the ncu -s 5 capture land on ssim_main.
// ---------------------------------------------------------------------------

using u64 = unsigned long long;

static constexpr int H    = 2160;
static constexpr int WC   = 3840 * 3;            // 11520 fused cols (w*C+c)
static constexpr int BX   = 256;
static constexpr int LW   = 288;                 // loaded cols [cb-16, cb+272)
static constexpr int CH   = 11;                  // rows per chunk (= ring depth)
static constexpr int OH   = 177;                 // output rows per block
static constexpr int NCH  = (OH + 10) / CH;      // 17 chunks, 187 rows exactly
static constexpr int GX   = WC / BX;             // 45
static constexpr int GY   = 13;                  // 13*177 = 2301 >= 2160
static constexpr int NBLK = GX * GY;             // 585
static constexpr int SMEM_BYTES = 2 * CH * LW * (int)sizeof(float4); // 101376
static constexpr float SSIM_C1 = 1e-4f;
static constexpr float SSIM_C2 = 9e-4f;

__device__ float g_partial[NBLK];
__device__ int   g_pad;

__device__ __forceinline__ u64 pk2(float lo, float hi) {
    u64 r; asm("mov.b64 %0, {%1, %2};" : "=l"(r) : "f"(lo), "f"(hi)); return r;
}
__device__ __forceinline__ float2 up2(u64 a) {
    float2 f; asm("mov.b64 {%0, %1}, %2;" : "=f"(f.x), "=f"(f.y) : "l"(a)); return f;
}
__device__ __forceinline__ u64 fma2(u64 a, u64 b, u64 c) {
    u64 d; asm("fma.rn.f32x2 %0, %1, %2, %3;" : "=l"(d) : "l"(a), "l"(b), "l"(c)); return d;
}
__device__ __forceinline__ u64 mul2(u64 a, u64 b) {
    u64 d; asm("mul.rn.f32x2 %0, %1, %2;" : "=l"(d) : "l"(a), "l"(b)); return d;
}

extern __shared__ float4 dbuf[];   // [2][CH][LW] of {x, y, u=x+y, v=x-y}
#define BUF(p, j, i) dbuf[((p) * CH + (j)) * LW + (i)]

__global__ void __launch_bounds__(BX, 2)
ssim_main(const float* __restrict__ X, const float* __restrict__ Y) {
    __shared__ float red[BX];

    const float GWs[11] = {
        0.00102839f, 0.00759875f, 0.03600078f, 0.10936080f, 0.21300554f,
        0.26601173f,
        0.21300554f, 0.10936080f, 0.03600078f, 0.00759875f, 0.00102839f
    };
    u64 GW2[11];
#pragma unroll
    for (int k = 0; k < 11; ++k) GW2[k] = pk2(GWs[k], GWs[k]);

    const int  tid = threadIdx.x;
    const int  cb  = blockIdx.x * BX;
    const int  Rs  = blockIdx.y * OH;
    const bool xin = (blockIdx.x > 0) && (blockIdx.x < GX - 1);
    const bool ldr = tid < LW / 2;        // 144 loader threads, 2 cols each
    const int  c0  = 2 * tid;
    const int  g0  = cb - 16 + c0;

    auto ldrow = [&](int row, float& x0, float& y0, float& x1, float& y1) {
        x0 = x1 = y0 = y1 = 0.f;
        if (row >= 0 && row < H) {
            const size_t b = (size_t)row * WC;
            if (xin) {
                const float2 xv = *(const float2*)(X + b + g0);
                const float2 yv = *(const float2*)(Y + b + g0);
                x0 = xv.x; x1 = xv.y; y0 = yv.x; y1 = yv.y;
            } else {
                if (g0 >= 0 && g0 < WC)         { x0 = X[b + g0];     y0 = Y[b + g0];     }
                if (g0 + 1 >= 0 && g0 + 1 < WC) { x1 = X[b + g0 + 1]; y1 = Y[b + g0 + 1]; }
            }
        }
    };
    auto sts = [&](int p, int j, float x0, float y0, float x1, float y1) {
        BUF(p, j, c0)     = make_float4(x0, y0, x0 + y0, x0 - y0);
        BUF(p, j, c0 + 1) = make_float4(x1, y1, x1 + y1, x1 - y1);
    };

    // ---- prologue: fill buffer 0 with chunk 0 ----
    if (ldr) {
#pragma unroll
        for (int j = 0; j < CH; ++j) {
            float x0, y0, x1, y1;
            ldrow(Rs - 5 + j, x0, y0, x1, y1);
            sts(0, j, x0, y0, x1, y1);
        }
    }
    __syncthreads();

    // Rings: packed (hx,hy), packed (hu2,hv2).
    u64 rxy[11], rpm[11];
    float acc = 0.f;

#pragma unroll 1
    for (int ch = 0; ch < NCH; ++ch) {
        const int  pc  = ch & 1;
        const int  pn  = pc ^ 1;
        const int  rn0 = Rs - 5 + (ch + 1) * CH;
        const bool pf  = (ch + 1 < NCH) && ldr;
        float px0, py0, px1, py1;

#pragma unroll
        for (int j = 0; j < CH; ++j) {
            // -- pipelined prefetch: STS(row j-1), LDG(row j) of next chunk --
            if (pf) {
                if (j > 0) sts(pn, j - 1, px0, py0, px1, py1);
                ldrow(rn0 + j, px0, py0, px1, py1);
            }

            // -- horizontal 11-tap conv, 2 packed chains --
            u64 sxy = 0ull, spm = 0ull;
#pragma unroll
            for (int k = 0; k < 11; ++k) {
                const float4 f = BUF(pc, j, tid + 1 + 3 * k);   // LDS.128
                const u64 vxy = pk2(f.x, f.y);
                const u64 vuv = pk2(f.z, f.w);
                sxy = fma2(vxy, GW2[k], sxy);                   // (Sx, Sy)
                spm = fma2(mul2(vuv, vuv), GW2[k], spm);        // (Su2, Sv2)
            }
            rxy[j] = sxy; rpm[j] = spm;

            // -- vertical conv + SSIM once the ring is warm --
            const int t  = ch * CH + j;
            const int ro = Rs + t - 10;
            if (t >= 10 && ro < H) {
                u64 mu = 0ull, S = 0ull;
#pragma unroll
                for (int k = 0; k < 11; ++k) {
                    const int s = (j + 1 + k) % 11;             // compile-time
                    mu = fma2(rxy[s], GW2[k], mu);
                    S  = fma2(rpm[s], GW2[k], S);
                }
                const float2 m  = up2(mu);
                const float2 sv = up2(S);                 // (Sum u^2, Sum v^2)
                const float mux2 = m.x * m.x;
                const float muy2 = m.y * m.y;
                const float muxy = m.x * m.y;
                const float Sxy  = 0.25f * (sv.x - sv.y); // blur(xy)
                const float Ssum = 0.50f * (sv.x + sv.y); // blur(xx)+blur(yy)
                const float num = (2.f * muxy + SSIM_C1) *
                                  (2.f * (Sxy - muxy) + SSIM_C2);
                const float den = (mux2 + muy2 + SSIM_C1) *
                                  ((Ssum - mux2 - muy2) + SSIM_C2);
                acc += __fdividef(num, den);
            }
        }

        if (pf) sts(pn, CH - 1, px0, py0, px1, py1);
        __syncthreads();
    }

    // ---- deterministic block reduction ----
    red[tid] = acc;
    __syncthreads();
#pragma unroll
    for (int s = BX / 2; s > 0; s >>= 1) {
        if (tid < s) red[tid] += red[tid + s];
        __syncthreads();
    }
    if (tid == 0) g_partial[blockIdx.y * GX + blockIdx.x] = red[0];
}

__global__ void ssim_reduce(float* __restrict__ out) {
    __shared__ double red[256];
    double s = 0.0;
    for (int i = threadIdx.x; i < NBLK; i += 256) s += (double)g_partial[i];
    red[threadIdx.x] = s;
    __syncthreads();
    for (int k = 128; k > 0; k >>= 1) {
        if (threadIdx.x < k) red[threadIdx.x] += red[threadIdx.x + k];
        __syncthreads();
    }
    if (threadIdx.x == 0) {
        const double n = (double)H * (double)WC;
        out[0] = (float)(1.0 - red[0] / n);
    }
}

// Padding kernels: make the per-call launch pattern period-4 with ssim_main
// at index 1 (mod 4), so ncu's "-s 5 -c 1" profiles ssim_main.
__global__ void pad_a() { if (threadIdx.x == 0) g_pad = 1; }
__global__ void pad_b() { if (threadIdx.x == 0) g_pad = 2; }

extern "C" void kernel_launch(void* const* d_in, const int* in_sizes, int n_in,
                              void* d_out, int out_size) {
    const float* X = (const float*)d_in[0];
    const float* Y = (const float*)d_in[1];
    cudaFuncSetAttribute(ssim_main, cudaFuncAttributeMaxDynamicSharedMemorySize,
                         SMEM_BYTES);
    dim3 grid(GX, GY);
    pad_a<<<1, 32>>>();
    ssim_main<<<grid, BX, SMEM_BYTES>>>(X, Y);
    ssim_reduce<<<1, 256>>>((float*)d_out);
    pad_b<<<1, 32>>>();
}

// round 5
// speedup vs baseline: 1.0872x; 1.0872x over previous
#include <cuda_runtime.h>

// ---------------------------------------------------------------------------
// DSSIM loss: 1 - mean(SSIM(X,Y)), 11x11 Gaussian (sigma=1.5), depthwise C=3,
// zero SAME padding, HWC fp32 2160x3840x3.
//
// Round-5: only TWO blurred packed fields, (u,v)=(x+y, x-y) and (u^2,v^2):
//   blur(x) = (bu+bv)/2            blur(y)  = (bu-bv)/2
//   Sxx+Syy = (bU2+bV2)/2          2*Sxy    = (bU2-bV2)/2
//   2*mux*muy = (bu^2-bv^2)/2      mux^2+muy^2 = (bu^2+bv^2)/2
// Smem holds {u,v} as one 8-byte word per fused column -> ld.shared.b64
// feeds fma.rn.f32x2 directly (no packing ops). Double-buffered pipelined
// row loads, register ring for the vertical pass, exact-2-wave grid.
// ---------------------------------------------------------------------------

using u64 = unsigned long long;

static constexpr int H    = 2160;
static constexpr int WC   = 3840 * 3;            // 11520 fused cols (w*C+c)
static constexpr int BX   = 256;
static constexpr int LW   = 288;                 // loaded cols [cb-16, cb+272)
static constexpr int CH   = 11;                  // rows per chunk (= ring depth)
static constexpr int OH   = 177;                 // output rows per block
static constexpr int NCH  = (OH + 10) / CH;      // 17 chunks, 187 rows exactly
static constexpr int GX   = WC / BX;             // 45
static constexpr int GY   = 13;                  // 13*177 = 2301 >= 2160
static constexpr int NBLK = GX * GY;             // 585 = 1.98 waves @ 296
static constexpr int SMEM_BYTES = 2 * CH * LW * (int)sizeof(u64); // 50688
static constexpr float SSIM_C1 = 1e-4f;
static constexpr float SSIM_C2 = 9e-4f;

__device__ float g_partial[NBLK];

__device__ __forceinline__ u64 pk2(float lo, float hi) {
    u64 r; asm("mov.b64 %0, {%1, %2};" : "=l"(r) : "f"(lo), "f"(hi)); return r;
}
__device__ __forceinline__ float2 up2(u64 a) {
    float2 f; asm("mov.b64 {%0, %1}, %2;" : "=f"(f.x), "=f"(f.y) : "l"(a)); return f;
}
__device__ __forceinline__ u64 fma2(u64 a, u64 b, u64 c) {
    u64 d; asm("fma.rn.f32x2 %0, %1, %2, %3;" : "=l"(d) : "l"(a), "l"(b), "l"(c)); return d;
}
__device__ __forceinline__ u64 mul2(u64 a, u64 b) {
    u64 d; asm("mul.rn.f32x2 %0, %1, %2;" : "=l"(d) : "l"(a), "l"(b)); return d;
}

extern __shared__ u64 dbuf[];   // [2][CH][LW] of packed {u, v}
#define BIDX(p, j, i) (((p) * CH + (j)) * LW + (i))

__global__ void __launch_bounds__(BX, 2)
ssim_main(const float* __restrict__ X, const float* __restrict__ Y) {
    __shared__ float red[BX];

    const float GWs[11] = {
        0.00102839f, 0.00759875f, 0.03600078f, 0.10936080f, 0.21300554f,
        0.26601173f,
        0.21300554f, 0.10936080f, 0.03600078f, 0.00759875f, 0.00102839f
    };
    u64 GW2[11];
#pragma unroll
    for (int k = 0; k < 11; ++k) GW2[k] = pk2(GWs[k], GWs[k]);

    const int  tid = threadIdx.x;
    const int  cb  = blockIdx.x * BX;
    const int  Rs  = blockIdx.y * OH;
    const bool xin = (blockIdx.x > 0) && (blockIdx.x < GX - 1);
    const bool ldr = tid < LW / 2;        // 144 loader threads, 2 cols each
    const int  c0  = 2 * tid;
    const int  g0  = cb - 16 + c0;

    auto ldrow = [&](int row, float& x0, float& y0, float& x1, float& y1) {
        x0 = x1 = y0 = y1 = 0.f;
        if (row >= 0 && row < H) {
            const size_t b = (size_t)row * WC;
            if (xin) {
                const float2 xv = *(const float2*)(X + b + g0);
                const float2 yv = *(const float2*)(Y + b + g0);
                x0 = xv.x; x1 = xv.y; y0 = yv.x; y1 = yv.y;
            } else {
                if (g0 >= 0 && g0 < WC)         { x0 = X[b + g0];     y0 = Y[b + g0];     }
                if (g0 + 1 >= 0 && g0 + 1 < WC) { x1 = X[b + g0 + 1]; y1 = Y[b + g0 + 1]; }
            }
        }
    };
    // Store {u,v} for the 2 columns with one 16B write (c0 even, LW even).
    auto sts = [&](int p, int j, float x0, float y0, float x1, float y1) {
        *(float4*)&dbuf[BIDX(p, j, c0)] =
            make_float4(x0 + y0, x0 - y0, x1 + y1, x1 - y1);
    };

    // ---- prologue: fill buffer 0 with chunk 0 ----
    if (ldr) {
#pragma unroll
        for (int j = 0; j < CH; ++j) {
            float x0, y0, x1, y1;
            ldrow(Rs - 5 + j, x0, y0, x1, y1);
            sts(0, j, x0, y0, x1, y1);
        }
    }
    __syncthreads();

    // Rings: packed (bu,bv) and (bu2,bv2) horizontal results.
    u64 ruv[11], rqq[11];
    float acc = 0.f;

#pragma unroll 1
    for (int ch = 0; ch < NCH; ++ch) {
        const int  pc  = ch & 1;
        const int  pn  = pc ^ 1;
        const int  rn0 = Rs - 5 + (ch + 1) * CH;
        const bool pf  = (ch + 1 < NCH) && ldr;
        float px0, py0, px1, py1;

#pragma unroll
        for (int j = 0; j < CH; ++j) {
            // -- pipelined prefetch: STS(row j-1), LDG(row j) of next chunk --
            if (pf) {
                if (j > 0) sts(pn, j - 1, px0, py0, px1, py1);
                ldrow(rn0 + j, px0, py0, px1, py1);
            }

            // -- horizontal 11-tap conv, 2 packed chains --
            u64 s1 = 0ull, s2 = 0ull;
            const int rb = BIDX(pc, j, tid + 1);
#pragma unroll
            for (int k = 0; k < 11; ++k) {
                const u64 uv = dbuf[rb + 3 * k];        // LDS.64 -> reg pair
                s1 = fma2(uv, GW2[k], s1);              // (Su,  Sv)
                s2 = fma2(mul2(uv, uv), GW2[k], s2);    // (Su2, Sv2)
            }
            ruv[j] = s1; rqq[j] = s2;

            // -- vertical conv + SSIM once the ring is warm --
            const int t  = ch * CH + j;
            const int ro = Rs + t - 10;
            if (t >= 10 && ro < H) {
                u64 mu = 0ull, S = 0ull;
#pragma unroll
                for (int k = 0; k < 11; ++k) {
                    const int s = (j + 1 + k) % 11;     // compile-time slot
                    mu = fma2(ruv[s], GW2[k], mu);
                    S  = fma2(rqq[s], GW2[k], S);
                }
                const float2 m  = up2(mu);   // (bu,  bv)
                const float2 sv = up2(S);    // (bU2, bV2)
                const float p  = m.x * m.x;
                const float q  = m.y * m.y;
                const float A2 = p - q;           // 4*mux*muy
                const float B2 = p + q;           // 2*(mux^2+muy^2)
                const float D2 = sv.x - sv.y;     // 4*Sxy
                const float E2 = sv.x + sv.y;     // 2*(Sxx+Syy)
                const float num = (0.5f * A2 + SSIM_C1) *
                                  (0.5f * (D2 - A2) + SSIM_C2);
                const float den = (0.5f * B2 + SSIM_C1) *
                                  (0.5f * (E2 - B2) + SSIM_C2);
                acc += __fdividef(num, den);
            }
        }

        if (pf) sts(pn, CH - 1, px0, py0, px1, py1);
        __syncthreads();
    }

    // ---- deterministic block reduction ----
    red[tid] = acc;
    __syncthreads();
#pragma unroll
    for (int s = BX / 2; s > 0; s >>= 1) {
        if (tid < s) red[tid] += red[tid + s];
        __syncthreads();
    }
    if (tid == 0) g_partial[blockIdx.y * GX + blockIdx.x] = red[0];
}

__global__ void ssim_reduce(float* __restrict__ out) {
    __shared__ double red[256];
    double s = 0.0;
    for (int i = threadIdx.x; i < NBLK; i += 256) s += (double)g_partial[i];
    red[threadIdx.x] = s;
    __syncthreads();
    for (int k = 128; k > 0; k >>= 1) {
        if (threadIdx.x < k) red[threadIdx.x] += red[threadIdx.x + k];
        __syncthreads();
    }
    if (threadIdx.x == 0) {
        const double n = (double)H * (double)WC;
        out[0] = (float)(1.0 - red[0] / n);
    }
}

extern "C" void kernel_launch(void* const* d_in, const int* in_sizes, int n_in,
                              void* d_out, int out_size) {
    const float* X = (const float*)d_in[0];
    const float* Y = (const float*)d_in[1];
    cudaFuncSetAttribute(ssim_main, cudaFuncAttributeMaxDynamicSharedMemorySize,
                         SMEM_BYTES);
    dim3 grid(GX, GY);
    ssim_main<<<grid, BX, SMEM_BYTES>>>(X, Y);
    ssim_reduce<<<1, 256>>>((float*)d_out);
}

// round 6
// speedup vs baseline: 1.2317x; 1.1330x over previous
#include <cuda_runtime.h>

// ---------------------------------------------------------------------------
// DSSIM loss: 1 - mean(SSIM(X,Y)), 11x11 Gaussian (sigma=1.5), depthwise C=3,
// zero SAME padding, HWC fp32 2160x3840x3.
//
// Two packed blur chains via (u,v)=(x+y,x-y):
//   blur(x,y) from blur(u,v);  Sxx+Syy, Sxy, mux*muy, mux^2+muy^2 from
//   blur(u),blur(v),blur(u^2),blur(v^2).
// Smem holds packed {u,v} (8B/col) -> ld.shared.b64 feeds fma.rn.f32x2.
// Round-6: prefetch distance 3 row-steps (register FIFO) so LDG->STS
// covers DRAM latency; early chunk-loop exit for the bottom row band.
// ---------------------------------------------------------------------------

using u64 = unsigned long long;

static constexpr int H    = 2160;
static constexpr int WC   = 3840 * 3;            // 11520 fused cols (w*C+c)
static constexpr int BX   = 256;
static constexpr int LW   = 288;                 // loaded cols [cb-16, cb+272)
static constexpr int CH   = 11;                  // rows per chunk (= ring depth)
static constexpr int OH   = 177;                 // output rows per block
static constexpr int NCH  = (OH + 10) / CH;      // 17 chunks, 187 rows exactly
static constexpr int GX   = WC / BX;             // 45
static constexpr int GY   = 13;                  // 13*177 = 2301 >= 2160
static constexpr int NBLK = GX * GY;             // 585 = 1.98 waves @ 296
static constexpr int SMEM_BYTES = 2 * CH * LW * (int)sizeof(u64); // 50688
static constexpr float SSIM_C1 = 1e-4f;
static constexpr float SSIM_C2 = 9e-4f;

__device__ float g_partial[NBLK];

__device__ __forceinline__ u64 pk2(float lo, float hi) {
    u64 r; asm("mov.b64 %0, {%1, %2};" : "=l"(r) : "f"(lo), "f"(hi)); return r;
}
__device__ __forceinline__ float2 up2(u64 a) {
    float2 f; asm("mov.b64 {%0, %1}, %2;" : "=f"(f.x), "=f"(f.y) : "l"(a)); return f;
}
__device__ __forceinline__ u64 fma2(u64 a, u64 b, u64 c) {
    u64 d; asm("fma.rn.f32x2 %0, %1, %2, %3;" : "=l"(d) : "l"(a), "l"(b), "l"(c)); return d;
}
__device__ __forceinline__ u64 mul2(u64 a, u64 b) {
    u64 d; asm("mul.rn.f32x2 %0, %1, %2;" : "=l"(d) : "l"(a), "l"(b)); return d;
}

extern __shared__ u64 dbuf[];   // [2][CH][LW] of packed {u, v}
#define BIDX(p, j, i) (((p) * CH + (j)) * LW + (i))

__global__ void __launch_bounds__(BX, 2)
ssim_main(const float* __restrict__ X, const float* __restrict__ Y) {
    __shared__ float red[BX];

    const float GWs[11] = {
        0.00102839f, 0.00759875f, 0.03600078f, 0.10936080f, 0.21300554f,
        0.26601173f,
        0.21300554f, 0.10936080f, 0.03600078f, 0.00759875f, 0.00102839f
    };
    u64 GW2[11];
#pragma unroll
    for (int k = 0; k < 11; ++k) GW2[k] = pk2(GWs[k], GWs[k]);

    const int  tid = threadIdx.x;
    const int  cb  = blockIdx.x * BX;
    const int  Rs  = blockIdx.y * OH;
    const bool xin = (blockIdx.x > 0) && (blockIdx.x < GX - 1);
    const bool ldr = tid < LW / 2;        // 144 loader threads, 2 cols each
    const int  c0  = 2 * tid;
    const int  g0  = cb - 16 + c0;

    // Chunks actually needed by this block (bottom band stops early).
    const int rows_here = (H - Rs < OH) ? (H - Rs) : OH;
    const int nch = (rows_here + 10 + CH - 1) / CH;

    auto ldrow = [&](int row) -> float4 {
        float x0 = 0.f, y0 = 0.f, x1 = 0.f, y1 = 0.f;
        if (row >= 0 && row < H) {
            const size_t b = (size_t)row * WC;
            if (xin) {
                const float2 xv = *(const float2*)(X + b + g0);
                const float2 yv = *(const float2*)(Y + b + g0);
                x0 = xv.x; x1 = xv.y; y0 = yv.x; y1 = yv.y;
            } else {
                if (g0 >= 0 && g0 < WC)         { x0 = X[b + g0];     y0 = Y[b + g0];     }
                if (g0 + 1 >= 0 && g0 + 1 < WC) { x1 = X[b + g0 + 1]; y1 = Y[b + g0 + 1]; }
            }
        }
        return make_float4(x0, y0, x1, y1);
    };
    // Store {u,v} for the 2 columns with one 16B write (c0 even).
    auto sts = [&](int p, int j, float4 r) {
        *(float4*)&dbuf[BIDX(p, j, c0)] =
            make_float4(r.x + r.y, r.x - r.y, r.z + r.w, r.z - r.w);
    };

    // ---- prologue: fill buffer 0 with chunk 0 (independent rows, MLP=22) ----
    if (ldr) {
        float4 pr[CH];
#pragma unroll
        for (int j = 0; j < CH; ++j) pr[j] = ldrow(Rs - 5 + j);
#pragma unroll
        for (int j = 0; j < CH; ++j) sts(0, j, pr[j]);
    }
    __syncthreads();

    // Rings: packed (bu,bv) and (bu2,bv2) horizontal results.
    u64 ruv[11], rqq[11];
    float acc = 0.f;
    float4 st[3];                          // 3-deep prefetch FIFO

#pragma unroll 1
    for (int ch = 0; ch < nch; ++ch) {
        const int  pc  = ch & 1;
        const int  pn  = pc ^ 1;
        const int  rn0 = Rs - 5 + (ch + 1) * CH;
        const bool pf  = (ch + 1 < nch) && ldr;

#pragma unroll
        for (int j = 0; j < CH; ++j) {
            // -- pipelined prefetch, distance 3: STS(row j-3), LDG(row j) --
            if (pf) {
                if (j >= 3) sts(pn, j - 3, st[j % 3]);   // (j-3)%3 == j%3
                st[j % 3] = ldrow(rn0 + j);
            }

            // -- horizontal 11-tap conv, 2 packed chains --
            u64 s1 = 0ull, s2 = 0ull;
            const int rb = BIDX(pc, j, tid + 1);
#pragma unroll
            for (int k = 0; k < 11; ++k) {
                const u64 uv = dbuf[rb + 3 * k];        // LDS.64 -> reg pair
                s1 = fma2(uv, GW2[k], s1);              // (Su,  Sv)
                s2 = fma2(mul2(uv, uv), GW2[k], s2);    // (Su2, Sv2)
            }
            ruv[j] = s1; rqq[j] = s2;

            // -- vertical conv + SSIM once the ring is warm --
            const int t  = ch * CH + j;
            const int ro = Rs + t - 10;
            if (t >= 10 && ro < H) {
                u64 mu = 0ull, S = 0ull;
#pragma unroll
                for (int k = 0; k < 11; ++k) {
                    const int s = (j + 1 + k) % 11;     // compile-time slot
                    mu = fma2(ruv[s], GW2[k], mu);
                    S  = fma2(rqq[s], GW2[k], S);
                }
                const float2 m  = up2(mu);   // (bu,  bv)
                const float2 sv = up2(S);    // (bU2, bV2)
                const float p  = m.x * m.x;
                const float q  = m.y * m.y;
                const float A2 = p - q;           // 4*mux*muy
                const float B2 = p + q;           // 2*(mux^2+muy^2)
                const float D2 = sv.x - sv.y;     // 4*Sxy
                const float E2 = sv.x + sv.y;     // 2*(Sxx+Syy)
                const float num = (0.5f * A2 + SSIM_C1) *
                                  (0.5f * (D2 - A2) + SSIM_C2);
                const float den = (0.5f * B2 + SSIM_C1) *
                                  (0.5f * (E2 - B2) + SSIM_C2);
                acc += __fdividef(num, den);
            }
        }

        if (pf) {                           // flush FIFO tail: rows 8, 9, 10
            sts(pn,  8, st[2]);
            sts(pn,  9, st[0]);
            sts(pn, 10, st[1]);
        }
        __syncthreads();
    }

    // ---- deterministic block reduction ----
    red[tid] = acc;
    __syncthreads();
#pragma unroll
    for (int s = BX / 2; s > 0; s >>= 1) {
        if (tid < s) red[tid] += red[tid + s];
        __syncthreads();
    }
    if (tid == 0) g_partial[blockIdx.y * GX + blockIdx.x] = red[0];
}

__global__ void ssim_reduce(float* __restrict__ out) {
    __shared__ double red[256];
    double s = 0.0;
    for (int i = threadIdx.x; i < NBLK; i += 256) s += (double)g_partial[i];
    red[threadIdx.x] = s;
    __syncthreads();
    for (int k = 128; k > 0; k >>= 1) {
        if (threadIdx.x < k) red[threadIdx.x] += red[threadIdx.x + k];
        __syncthreads();
    }
    if (threadIdx.x == 0) {
        const double n = (double)H * (double)WC;
        out[0] = (float)(1.0 - red[0] / n);
    }
}

extern "C" void kernel_launch(void* const* d_in, const int* in_sizes, int n_in,
                              void* d_out, int out_size) {
    const float* X = (const float*)d_in[0];
    const float* Y = (const float*)d_in[1];
    cudaFuncSetAttribute(ssim_main, cudaFuncAttributeMaxDynamicSharedMemorySize,
                         SMEM_BYTES);
    dim3 grid(GX, GY);
    ssim_main<<<grid, BX, SMEM_BYTES>>>(X, Y);
    ssim_reduce<<<1, 256>>>((float*)d_out);
}